// round 14
// baseline (speedup 1.0000x reference)
#include <cuda_runtime.h>
#include <cstdint>

#define NM 4
#define NB 64
#define NL 512
#define NQ 512
#define NS 26
#define NSL 16          // slices per model (32 p each)
#define NTH 256
#define PTH 256

// SMEM byte offsets (base 1024-aligned)
#define OFF_ALP  0            // 64 rows x 1040 B (512 bf16 + 16B pad)
#define OFF_INP  66560        // 2 bufs x 64 rows x 80 B
#define OFF_PART 76800        // 4 kq x 32 p x 72 f32      (36864 B)
#define OFF_E    113664       // 32 p x 72 f32             (9216 B)
#define OFF_PUB  122880       // 16 x 64 f32               (4096 B)
#define OFF_INV  126976       // 64 f32
#define SMEM_BYTES 127232

#define ALP_STR  1040         // bytes per alpha row
#define INP_STR  80           // bytes per inp row
#define PRT_PSTR 72           // f32 words per p row
#define PRT_KSTR 2304         // f32 words per kq block (32*72)

// ---------------- device scratch ---------------------------------------------
__device__ float g_A[NM * NQ * NQ];
__device__ float g_pi[NM * NQ];
__device__ float g_Bem[NM * NQ * NS];
__device__ unsigned short g_alphab[NM * 2 * NB * NQ];  // bf16 alpha, dbl-buffered
__device__ float g_part[NM * NB * 32];                 // per-slice partial sums
__device__ int   g_ctr[NM * 32];

// ---------------- helpers ----------------------------------------------------
__device__ __forceinline__ uint32_t smem_u32(const void* p) {
    uint32_t a;
    asm("{ .reg .u64 t; cvta.to.shared.u64 t, %1; cvt.u32.u64 %0, t; }" : "=r"(a) : "l"(p));
    return a;
}
__device__ __forceinline__ void cp16(uint32_t dst, const void* src) {
    asm volatile("cp.async.cg.shared.global [%0], [%1], 16;" :: "r"(dst), "l"(src) : "memory");
}
#define CP_COMMIT()  asm volatile("cp.async.commit_group;" ::: "memory")
#define CP_WAIT0()   asm volatile("cp.async.wait_group 0;" ::: "memory")

__device__ __forceinline__ unsigned packbf(float lo, float hi) {
    unsigned r;
    asm("cvt.rn.bf16x2.f32 %0, %1, %2;" : "=r"(r) : "f"(hi), "f"(lo));
    return r;
}
__device__ __forceinline__ float bf2f(unsigned short u) {
    return __uint_as_float(((unsigned)u) << 16);
}
__device__ __forceinline__ void mma16816(float* d, const uint32_t* a,
                                         uint32_t b0, uint32_t b1) {
    asm volatile(
        "mma.sync.aligned.m16n8k16.row.col.f32.bf16.bf16.f32 "
        "{%0,%1,%2,%3}, {%4,%5,%6,%7}, {%8,%9}, {%0,%1,%2,%3};"
        : "+f"(d[0]), "+f"(d[1]), "+f"(d[2]), "+f"(d[3])
        : "r"(a[0]), "r"(a[1]), "r"(a[2]), "r"(a[3]), "r"(b0), "r"(b1));
}
__device__ __forceinline__ uint32_t lds32(uint32_t addr) {
    uint32_t v;
    asm volatile("ld.shared.b32 %0, [%1];" : "=r"(v) : "r"(addr) : "memory");
    return v;
}
__device__ __forceinline__ void lds64f(float& x, float& y, uint32_t addr) {
    asm volatile("ld.shared.v2.f32 {%0,%1}, [%2];" : "=f"(x), "=f"(y) : "r"(addr) : "memory");
}
__device__ __forceinline__ void sts64f(uint32_t addr, float x, float y) {
    asm volatile("st.shared.v2.f32 [%0], {%1,%2};" :: "r"(addr), "f"(x), "f"(y) : "memory");
}
__device__ __forceinline__ void sts32(uint32_t addr, uint32_t v) {
    asm volatile("st.shared.b32 [%0], %1;" :: "r"(addr), "r"(v) : "memory");
}
__device__ __forceinline__ float ldsf(uint32_t addr) {
    float v;
    asm volatile("ld.shared.f32 %0, [%1];" : "=f"(v) : "r"(addr) : "memory");
    return v;
}

// grid barrier: 16 CTAs of one model (all resident; 64 CTAs <= 148 SMs).
// Visibility: STG -> bar.sync -> red.release (tid0) -> ld.acquire -> bar.sync
// is a complete happens-before chain per the PTX memory model.
__device__ __forceinline__ void gbar(int* c, int target) {
    __syncthreads();
    if (threadIdx.x == 0) {
        asm volatile("red.release.gpu.global.add.s32 [%0], 1;" :: "l"(c) : "memory");
        int v;
        do {
            asm volatile("ld.acquire.gpu.global.b32 %0, [%1];" : "=r"(v) : "l"(c) : "memory");
        } while (v < target);
    }
    __syncthreads();
}

// ---------------- fused preprocessing ----------------------------------------
__global__ void pre_k(const float* __restrict__ Al, const float* __restrict__ pil,
                      const float* __restrict__ eml) {
    int r = blockIdx.x, tid = threadIdx.x;
    if (r == 0) {
        if (tid < NM * 32) g_ctr[tid] = 0;
        for (int i = tid; i < NM * NB * 32; i += PTH) g_part[i] = 0.f;
    }
    const float* x; float* y; int len;
    if (r < NM * NQ)           { x = Al  + (size_t)r * NQ; y = g_A  + (size_t)r * NQ; len = NQ; }
    else if (r < NM * NQ + NM) { int rr = r - NM * NQ;
                                 x = pil + (size_t)rr * NQ; y = g_pi + (size_t)rr * NQ; len = NQ; }
    else                       { int rr = r - NM * NQ - NM;
                                 x = eml + (size_t)rr * NS; y = g_Bem + (size_t)rr * NS; len = NS; }
    __shared__ float red[PTH];
    float mx = -1e30f;
    for (int i = tid; i < len; i += PTH) mx = fmaxf(mx, x[i]);
    red[tid] = mx; __syncthreads();
    for (int o = PTH / 2; o > 0; o >>= 1) {
        if (tid < o) red[tid] = fmaxf(red[tid], red[tid + o]);
        __syncthreads();
    }
    mx = red[0]; __syncthreads();
    float sm = 0.f;
    for (int i = tid; i < len; i += PTH) sm += expf(x[i] - mx);
    red[tid] = sm; __syncthreads();
    for (int o = PTH / 2; o > 0; o >>= 1) {
        if (tid < o) red[tid] += red[tid + o];
        __syncthreads();
    }
    float inv = 1.0f / red[0];
    for (int i = tid; i < len; i += PTH) y[i] = expf(x[i] - mx) * inv;
}

// ---------------- main persistent kernel --------------------------------------
// grid 64 = 4 models x 16 slices (32 p each); 256 threads = 8 warps:
// warp wid = nh*4 + kq: nh = 32-batch half, kq = 128-q quarter.
// Each warp computes 2 m-tiles (16p each) sharing the same B fragments.
__global__ void __launch_bounds__(NTH, 1)
hmm_fwd(const float* __restrict__ inputs, float* __restrict__ out) {
    const int m     = blockIdx.x >> 4;
    const int slice = blockIdx.x & 15;
    const int p0    = slice * 32;
    const int tid   = threadIdx.x;
    const int wid   = tid >> 5;
    const int lane  = tid & 31;
    const int g     = lane >> 2;
    const int t4    = lane & 3;
    const int nh    = wid >> 2;
    const int kq    = wid & 3;

    extern __shared__ __align__(1024) char smc[];
    const uint32_t su     = smem_u32(smc);
    const uint32_t alp_u  = su + OFF_ALP;
    const uint32_t inp_u  = su + OFF_INP;
    const uint32_t part_u = su + OFF_PART;
    const uint32_t e_u    = su + OFF_E;
    const uint32_t pub_u  = su + OFF_PUB;
    const uint32_t inv_u  = su + OFF_INV;

    // ---- persistent A fragments: af[mt][kk], A_sl[p][q] = g_A[m][q][p0+mt*16+p]
    uint32_t af[2][8][4];
    {
        const float* Ag = g_A + (size_t)m * NQ * NQ;
        #pragma unroll
        for (int mt = 0; mt < 2; ++mt) {
            int pw = p0 + mt * 16;
            #pragma unroll
            for (int kk = 0; kk < 8; ++kk) {
                int q0 = kq * 128 + kk * 16;
                af[mt][kk][0] = packbf(__ldg(Ag + (size_t)(q0 + 2*t4) * NQ + pw + g),
                                       __ldg(Ag + (size_t)(q0 + 2*t4 + 1) * NQ + pw + g));
                af[mt][kk][1] = packbf(__ldg(Ag + (size_t)(q0 + 2*t4) * NQ + pw + g + 8),
                                       __ldg(Ag + (size_t)(q0 + 2*t4 + 1) * NQ + pw + g + 8));
                af[mt][kk][2] = packbf(__ldg(Ag + (size_t)(q0 + 8 + 2*t4) * NQ + pw + g),
                                       __ldg(Ag + (size_t)(q0 + 9 + 2*t4) * NQ + pw + g));
                af[mt][kk][3] = packbf(__ldg(Ag + (size_t)(q0 + 8 + 2*t4) * NQ + pw + g + 8),
                                       __ldg(Ag + (size_t)(q0 + 9 + 2*t4) * NQ + pw + g + 8));
            }
        }
    }
    // ---- Bem fragments (emission HMMA; kq==0 warps only) ----
    uint32_t bem[2][2][4];
    if (kq == 0) {
        #pragma unroll
        for (int mt = 0; mt < 2; ++mt) {
            int pw = p0 + mt * 16;
            #pragma unroll
            for (int kk = 0; kk < 2; ++kk) {
                int s0 = kk * 16;
                auto gB = [&](int p, int s) -> float {
                    return (s < NS) ? g_Bem[((size_t)m * NQ + pw + p) * NS + s] : 0.f;
                };
                bem[mt][kk][0] = packbf(gB(g, s0 + 2*t4),     gB(g, s0 + 2*t4 + 1));
                bem[mt][kk][1] = packbf(gB(g + 8, s0 + 2*t4), gB(g + 8, s0 + 2*t4 + 1));
                bem[mt][kk][2] = packbf(gB(g, s0 + 8 + 2*t4), gB(g, s0 + 9 + 2*t4));
                bem[mt][kk][3] = packbf(gB(g + 8, s0 + 8 + 2*t4), gB(g + 8, s0 + 9 + 2*t4));
            }
        }
    }

    // zero inp buffers (pads must be zero), then order before stage_inp stores.
    for (int i = tid; i < 2560; i += NTH) sts32(inp_u + i * 4, 0u);
    __syncthreads();

    const float* inp_m = inputs + (size_t)m * NB * NL * NS;
    int* ctr = &g_ctr[m * 32];
    unsigned short* gA0 = g_alphab + (size_t)(m * 2 + 0) * NB * NQ;
    unsigned short* gA1 = g_alphab + (size_t)(m * 2 + 1) * NB * NQ;

    // epilogue cell mapping: thread owns 2 p (of 32), 4 b (of 64)
    const int pc = (tid & 15) * 2;
    const int bc = (tid >> 4) * 4;
    float ll = 0.f;

    auto stage_inp = [&](int t, int buf) {
        #pragma unroll
        for (int j = 0; j < 4; ++j) {
            int idx = j * NTH + tid;
            if (idx < 832) {
                int b = idx / 13, k = idx - b * 13;
                float2 v = __ldg((const float2*)(inp_m + (size_t)b * NL * NS +
                                                 (size_t)t * NS + k * 2));
                sts32(inp_u + buf * 5120 + b * INP_STR + k * 4, packbf(v.x, v.y));
            }
        }
    };

    // ---- t = 0 : alpha0 = pi * e0 (SIMT, one-time) ----
    stage_inp(0, 0);
    stage_inp(1, 1);
    __syncthreads();
    {
        float e[2][4] = {{0.f,0.f,0.f,0.f},{0.f,0.f,0.f,0.f}};
        for (int s = 0; s < NS; ++s) {
            float B0 = g_Bem[((size_t)m * NQ + p0 + pc) * NS + s];
            float B1 = g_Bem[((size_t)m * NQ + p0 + pc + 1) * NS + s];
            #pragma unroll
            for (int j = 0; j < 4; ++j) {
                unsigned short u = *(unsigned short*)(smc + OFF_INP + (bc + j) * INP_STR + s * 2);
                float x = bf2f(u);
                e[0][j] += B0 * x; e[1][j] += B1 * x;
            }
        }
        float pi0 = g_pi[m * NQ + p0 + pc], pi1 = g_pi[m * NQ + p0 + pc + 1];
        #pragma unroll
        for (int j = 0; j < 4; ++j) {
            unsigned pk = packbf(pi0 * e[0][j], pi1 * e[1][j]);
            *(unsigned*)(gA0 + (size_t)(bc + j) * NQ + p0 + pc) = pk;
            sts32(alp_u + (bc + j) * ALP_STR + (p0 + pc) * 2, pk);
        }
    }
    gbar(ctr, NSL);

    // ---- t = 1 .. 511 ----
    #pragma unroll 1
    for (int t = 1; t < NL; ++t) {
        const int dstb = t & 1;
        const unsigned short* srcg = dstb ? gA0 : gA1;
        unsigned short*       dstg = dstb ? gA1 : gA0;
        const bool resc = (t & 15) == 0;
        const bool pub  = (t & 15) == 15;

        // 1) pull alpha(t-1) into SMEM, skipping own slab (already stored locally)
        #pragma unroll
        for (int k = 0; k < 16; ++k) {
            int idx = k * NTH + tid;
            int b = idx >> 6, o = idx & 63;
            if ((o >> 2) != slice)
                cp16(alp_u + b * ALP_STR + o * 16, srcg + (size_t)b * NQ + o * 8);
        }
        CP_COMMIT();

        // 2) stage inputs for t+1
        stage_inp(t + 1 < NL ? t + 1 : NL - 1, (t + 1) & 1);

        // 3) deferred rescale factors (pub writes ordered by previous gbar)
        if (resc && tid < NB) {
            float s = 0.f;
            const float4* pp = (const float4*)&g_part[(m * NB + tid) * 32];
            #pragma unroll
            for (int k = 0; k < 4; ++k) {
                float4 v = __ldcg(pp + k);
                s += (v.x + v.y) + (v.z + v.w);
            }
            *(float*)(smc + OFF_INV + tid * 4) = 1.0f / s;
            if (slice == 0) ll += logf(s);
        }

        // 4) emission HMMA (kq==0 warps; inp(t) staged last iteration)
        if (kq == 0) {
            float ea[2][4][4];
            #pragma unroll
            for (int mt = 0; mt < 2; ++mt)
                #pragma unroll
                for (int nt = 0; nt < 4; ++nt)
                    #pragma unroll
                    for (int i = 0; i < 4; ++i) ea[mt][nt][i] = 0.f;
            uint32_t ibase = inp_u + (t & 1) * 5120 + (nh * 32 + g) * INP_STR + t4 * 4;
            #pragma unroll
            for (int nt = 0; nt < 4; ++nt) {
                uint32_t ba = ibase + nt * 8 * INP_STR;
                #pragma unroll
                for (int kk = 0; kk < 2; ++kk) {
                    uint32_t b0 = lds32(ba + kk * 32);
                    uint32_t b1 = lds32(ba + kk * 32 + 16);
                    mma16816(ea[0][nt], bem[0][kk], b0, b1);
                    mma16816(ea[1][nt], bem[1][kk], b0, b1);
                }
            }
            #pragma unroll
            for (int mt = 0; mt < 2; ++mt)
                #pragma unroll
                for (int nt = 0; nt < 4; ++nt) {
                    uint32_t wbase = e_u + ((mt*16 + g) * PRT_PSTR + nh*32 + nt*8 + t4*2) * 4;
                    sts64f(wbase, ea[mt][nt][0], ea[mt][nt][1]);
                    sts64f(wbase + 8 * PRT_PSTR * 4, ea[mt][nt][2], ea[mt][nt][3]);
                }
        }

        CP_WAIT0();
        __syncthreads();

        // 5) main HMMA: 2 m-tiles x 4 n-tiles x 8 k-steps, B shared across m-tiles
        {
            float da[2][4][4];
            #pragma unroll
            for (int mt = 0; mt < 2; ++mt)
                #pragma unroll
                for (int nt = 0; nt < 4; ++nt)
                    #pragma unroll
                    for (int i = 0; i < 4; ++i) da[mt][nt][i] = 0.f;
            uint32_t bbase = alp_u + (nh * 32 + g) * ALP_STR + kq * 256 + t4 * 4;
            #pragma unroll
            for (int nt = 0; nt < 4; ++nt) {
                uint32_t ba = bbase + nt * 8 * ALP_STR;
                #pragma unroll
                for (int kk = 0; kk < 8; ++kk) {
                    uint32_t b0 = lds32(ba + kk * 32);
                    uint32_t b1 = lds32(ba + kk * 32 + 16);
                    mma16816(da[0][nt], af[0][kk], b0, b1);
                    mma16816(da[1][nt], af[1][kk], b0, b1);
                }
            }
            #pragma unroll
            for (int mt = 0; mt < 2; ++mt)
                #pragma unroll
                for (int nt = 0; nt < 4; ++nt) {
                    uint32_t wbase = part_u +
                        (kq * PRT_KSTR + (mt*16 + g) * PRT_PSTR + nh*32 + nt*8 + t4*2) * 4;
                    sts64f(wbase, da[mt][nt][0], da[mt][nt][1]);
                    sts64f(wbase + 8 * PRT_PSTR * 4, da[mt][nt][2], da[mt][nt][3]);
                }
        }
        __syncthreads();

        // 6) reduce 4 kq partials, multiply emission (+1/s), store bf16 alpha
        {
            float val[2][4];
            #pragma unroll
            for (int i = 0; i < 2; ++i) {
                float d[4] = {0.f, 0.f, 0.f, 0.f};
                float x, y;
                #pragma unroll
                for (int k2 = 0; k2 < 4; ++k2)
                    #pragma unroll
                    for (int jj = 0; jj < 2; ++jj) {
                        lds64f(x, y, part_u + (k2 * PRT_KSTR + (pc + i) * PRT_PSTR + bc + 2*jj) * 4);
                        d[2*jj] += x; d[2*jj + 1] += y;
                    }
                #pragma unroll
                for (int jj = 0; jj < 2; ++jj) {
                    lds64f(x, y, e_u + ((pc + i) * PRT_PSTR + bc + 2*jj) * 4);
                    val[i][2*jj] = d[2*jj] * x; val[i][2*jj + 1] = d[2*jj + 1] * y;
                }
            }
            if (resc) {
                #pragma unroll
                for (int j = 0; j < 4; ++j) {
                    float f = ldsf(inv_u + (bc + j) * 4);
                    val[0][j] *= f; val[1][j] *= f;
                }
            }
            #pragma unroll
            for (int j = 0; j < 4; ++j) {
                unsigned pk = packbf(val[0][j], val[1][j]);
                *(unsigned*)(dstg + (size_t)(bc + j) * NQ + p0 + pc) = pk;
                sts32(alp_u + (bc + j) * ALP_STR + (p0 + pc) * 2, pk);
            }
            if (pub) {
                #pragma unroll
                for (int j = 0; j < 4; ++j)
                    sts32(pub_u + ((tid & 15) * 64 + bc + j) * 4,
                          __float_as_uint(val[0][j] + val[1][j]));
                __syncthreads();
                if (tid < NB) {
                    float s = 0.f;
                    #pragma unroll
                    for (int k = 0; k < 16; ++k)
                        s += ldsf(pub_u + (k * 64 + tid) * 4);
                    g_part[(m * NB + tid) * 32 + slice] = s;
                }
            }
        }
        gbar(ctr, NSL * (t + 1));
    }

    // ---- finalize loglik ----
    if (slice == 0 && tid < NB) {
        float s = 0.f;
        const float4* pp = (const float4*)&g_part[(m * NB + tid) * 32];
        #pragma unroll
        for (int k = 0; k < 4; ++k) {
            float4 v = __ldcg(pp + k);
            s += (v.x + v.y) + (v.z + v.w);
        }
        out[m * NB + tid] = ll + logf(s);
    }
}

// ---------------- launch ------------------------------------------------------
extern "C" void kernel_launch(void* const* d_in, const int* in_sizes, int n_in,
                              void* d_out, int out_size) {
    (void)in_sizes; (void)n_in; (void)out_size;
    const float* inputs      = (const float*)d_in[0];
    const float* A_logits    = (const float*)d_in[1];
    const float* init_logits = (const float*)d_in[2];
    const float* em_logits   = (const float*)d_in[3];
    float* out = (float*)d_out;

    cudaFuncSetAttribute(hmm_fwd, cudaFuncAttributeMaxDynamicSharedMemorySize,
                         SMEM_BYTES);

    pre_k<<<NM * NQ + NM + NM * NQ, PTH>>>(A_logits, init_logits, em_logits);
    hmm_fwd<<<NM * NSL, NTH, SMEM_BYTES>>>(inputs, out);
}

// round 16
// speedup vs baseline: 1.1101x; 1.1101x over previous
#include <cuda_runtime.h>
#include <cstdint>

#define NM 4
#define NB 64
#define NL 512
#define NQ 512
#define NS 26
#define NTH 256
#define PTH 256

// SMEM byte offsets (base is 1024-aligned)
#define OFF_ALP  0            // 64 rows x 1040 B (512 bf16 + 8 pad)
#define OFF_INP  66560        // 2 bufs x 64 rows x 80 B
#define OFF_PART 76800        // 4 kq x 16 p x 72 f32
#define OFF_E    95232        // 16 p x 72 f32
#define OFF_PUB  99840        // 8 x 64 f32
#define OFF_INV  101888       // 64 f32
#define SMEM_BYTES 102400

#define ALP_STR  1040
#define INP_STR  80
#define PRT_PSTR 72
#define PRT_KSTR 1152

// ---------------- device scratch ---------------------------------------------
__device__ float g_A[NM * NQ * NQ];
__device__ float g_pi[NM * NQ];
__device__ float g_Bem[NM * NQ * NS];
__device__ unsigned short g_alphab[NM * 2 * NB * NQ];  // bf16 alpha, dbl-buffered
__device__ float g_part[NM * NB * 32];                 // per-slice partial sums
__device__ int   g_flag[NM * 2 * 32 * 32];             // padded flags: one 128B line each

// ---------------- helpers ----------------------------------------------------
__device__ __forceinline__ uint32_t smem_u32(const void* p) {
    uint32_t a;
    asm("{ .reg .u64 t; cvta.to.shared.u64 t, %1; cvt.u32.u64 %0, t; }" : "=r"(a) : "l"(p));
    return a;
}
__device__ __forceinline__ void cp16(uint32_t dst, const void* src) {
    asm volatile("cp.async.cg.shared.global [%0], [%1], 16;" :: "r"(dst), "l"(src) : "memory");
}
#define CP_COMMIT()  asm volatile("cp.async.commit_group;" ::: "memory")
#define CP_WAIT0()   asm volatile("cp.async.wait_group 0;" ::: "memory")

__device__ __forceinline__ unsigned packbf(float lo, float hi) {
    unsigned r;
    asm("cvt.rn.bf16x2.f32 %0, %1, %2;" : "=r"(r) : "f"(hi), "f"(lo));
    return r;
}
__device__ __forceinline__ float bf2f(unsigned short u) {
    return __uint_as_float(((unsigned)u) << 16);
}
__device__ __forceinline__ void mma16816(float* d, const uint32_t* a,
                                         uint32_t b0, uint32_t b1) {
    asm volatile(
        "mma.sync.aligned.m16n8k16.row.col.f32.bf16.bf16.f32 "
        "{%0,%1,%2,%3}, {%4,%5,%6,%7}, {%8,%9}, {%0,%1,%2,%3};"
        : "+f"(d[0]), "+f"(d[1]), "+f"(d[2]), "+f"(d[3])
        : "r"(a[0]), "r"(a[1]), "r"(a[2]), "r"(a[3]), "r"(b0), "r"(b1));
}
__device__ __forceinline__ uint32_t lds32(uint32_t addr) {
    uint32_t v;
    asm volatile("ld.shared.b32 %0, [%1];" : "=r"(v) : "r"(addr) : "memory");
    return v;
}
__device__ __forceinline__ void lds64f(float& x, float& y, uint32_t addr) {
    asm volatile("ld.shared.v2.f32 {%0,%1}, [%2];" : "=f"(x), "=f"(y) : "r"(addr) : "memory");
}
__device__ __forceinline__ void sts64f(uint32_t addr, float x, float y) {
    asm volatile("st.shared.v2.f32 [%0], {%1,%2};" :: "r"(addr), "f"(x), "f"(y) : "memory");
}
__device__ __forceinline__ void sts32(uint32_t addr, uint32_t v) {
    asm volatile("st.shared.b32 [%0], %1;" :: "r"(addr), "r"(v) : "memory");
}
__device__ __forceinline__ void st_release(int* p, int v) {
    asm volatile("st.release.gpu.global.s32 [%0], %1;" :: "l"(p), "r"(v) : "memory");
}
__device__ __forceinline__ int ld_acquire(const int* p) {
    int v;
    asm volatile("ld.acquire.gpu.global.s32 %0, [%1];" : "=r"(v) : "l"(p) : "memory");
    return v;
}

// ---------------- fused preprocessing ----------------------------------------
__global__ void pre_k(const float* __restrict__ Al, const float* __restrict__ pil,
                      const float* __restrict__ eml) {
    int r = blockIdx.x, tid = threadIdx.x;
    if (r == 0) {
        for (int i = tid; i < NM * 2 * 32 * 32; i += PTH) g_flag[i] = -1;
        for (int i = tid; i < NM * NB * 32; i += PTH) g_part[i] = 0.f;
    }
    const float* x; float* y; int len;
    if (r < NM * NQ)           { x = Al  + (size_t)r * NQ; y = g_A  + (size_t)r * NQ; len = NQ; }
    else if (r < NM * NQ + NM) { int rr = r - NM * NQ;
                                 x = pil + (size_t)rr * NQ; y = g_pi + (size_t)rr * NQ; len = NQ; }
    else                       { int rr = r - NM * NQ - NM;
                                 x = eml + (size_t)rr * NS; y = g_Bem + (size_t)rr * NS; len = NS; }
    __shared__ float red[PTH];
    float mx = -1e30f;
    for (int i = tid; i < len; i += PTH) mx = fmaxf(mx, x[i]);
    red[tid] = mx; __syncthreads();
    for (int o = PTH / 2; o > 0; o >>= 1) {
        if (tid < o) red[tid] = fmaxf(red[tid], red[tid + o]);
        __syncthreads();
    }
    mx = red[0]; __syncthreads();
    float sm = 0.f;
    for (int i = tid; i < len; i += PTH) sm += expf(x[i] - mx);
    red[tid] = sm; __syncthreads();
    for (int o = PTH / 2; o > 0; o >>= 1) {
        if (tid < o) red[tid] += red[tid + o];
        __syncthreads();
    }
    float inv = 1.0f / red[0];
    for (int i = tid; i < len; i += PTH) y[i] = expf(x[i] - mx) * inv;
}

// ---------------- main persistent kernel --------------------------------------
// grid 128 = 4 models x 32 slices (16 p each); 256 threads = 8 warps:
// warp wid = nh*4 + kq: nh in {0,1} = 32-batch half, kq in {0..3} = 128-q quarter.
__global__ void __launch_bounds__(NTH, 1)
hmm_fwd(const float* __restrict__ inputs, float* __restrict__ out) {
    const int m     = blockIdx.x >> 5;
    const int slice = blockIdx.x & 31;
    const int p0    = slice * 16;
    const int tid   = threadIdx.x;
    const int wid   = tid >> 5;
    const int lane  = tid & 31;
    const int g     = lane >> 2;
    const int t4    = lane & 3;
    const int nh    = wid >> 2;
    const int kq    = wid & 3;

    extern __shared__ __align__(1024) char smc[];
    const uint32_t su     = smem_u32(smc);
    const uint32_t alp_u  = su + OFF_ALP;
    const uint32_t inp_u  = su + OFF_INP;
    const uint32_t part_u = su + OFF_PART;
    const uint32_t e_u    = su + OFF_E;

    // ---- persistent A fragments (A_sl[p][q] = g_A[m][q][p0+p]) ----
    uint32_t af[8][4];
    {
        const float* Ag = g_A + (size_t)m * NQ * NQ;
        #pragma unroll
        for (int kk = 0; kk < 8; ++kk) {
            int q0 = kq * 128 + kk * 16;
            af[kk][0] = packbf(__ldg(Ag + (size_t)(q0 + 2*t4) * NQ + p0 + g),
                               __ldg(Ag + (size_t)(q0 + 2*t4 + 1) * NQ + p0 + g));
            af[kk][1] = packbf(__ldg(Ag + (size_t)(q0 + 2*t4) * NQ + p0 + g + 8),
                               __ldg(Ag + (size_t)(q0 + 2*t4 + 1) * NQ + p0 + g + 8));
            af[kk][2] = packbf(__ldg(Ag + (size_t)(q0 + 8 + 2*t4) * NQ + p0 + g),
                               __ldg(Ag + (size_t)(q0 + 9 + 2*t4) * NQ + p0 + g));
            af[kk][3] = packbf(__ldg(Ag + (size_t)(q0 + 8 + 2*t4) * NQ + p0 + g + 8),
                               __ldg(Ag + (size_t)(q0 + 9 + 2*t4) * NQ + p0 + g + 8));
        }
    }
    // ---- Bem fragments for emission HMMA (kq==0 warps only) ----
    uint32_t bem[2][4];
    if (kq == 0) {
        #pragma unroll
        for (int kk = 0; kk < 2; ++kk) {
            int s0 = kk * 16;
            auto gB = [&](int p, int s) -> float {
                return (s < NS) ? g_Bem[((size_t)m * NQ + p0 + p) * NS + s] : 0.f;
            };
            bem[kk][0] = packbf(gB(g, s0 + 2*t4),     gB(g, s0 + 2*t4 + 1));
            bem[kk][1] = packbf(gB(g + 8, s0 + 2*t4), gB(g + 8, s0 + 2*t4 + 1));
            bem[kk][2] = packbf(gB(g, s0 + 8 + 2*t4), gB(g, s0 + 9 + 2*t4));
            bem[kk][3] = packbf(gB(g + 8, s0 + 8 + 2*t4), gB(g + 8, s0 + 9 + 2*t4));
        }
    }

    // zero inp buffers (pads must be zero), then order before stage_inp stores.
    for (int i = tid; i < 2560; i += NTH) sts32(inp_u + i * 4, 0u);
    __syncthreads();

    const float* inp_m = inputs + (size_t)m * NB * NL * NS;
    int* flags = &g_flag[m * 2 * 32 * 32];      // [par][slice] stride 32 ints
    unsigned short* gA0 = g_alphab + (size_t)(m * 2 + 0) * NB * NQ;
    unsigned short* gA1 = g_alphab + (size_t)(m * 2 + 1) * NB * NQ;

    const int pc = (tid & 7) * 2;
    const int bc = (tid >> 3) * 2;
    float ll = 0.f;

    auto stage_inp = [&](int t, int buf) {
        #pragma unroll
        for (int j = 0; j < 4; ++j) {
            int idx = j * NTH + tid;
            if (idx < 832) {
                int b = idx / 13, k = idx - b * 13;
                float2 v = __ldg((const float2*)(inp_m + (size_t)b * NL * NS +
                                                 (size_t)t * NS + k * 2));
                sts32(inp_u + buf * 5120 + b * INP_STR + k * 4, packbf(v.x, v.y));
            }
        }
    };
    // arrive: publish this CTA's step-t output (all threads' STGs ordered by bar)
    auto arrive = [&](int t) {
        __syncthreads();
        if (tid == 0) st_release(&flags[((t & 1) * 32 + slice) * 32], t);
    };
    // wait: all 32 producer flags of step t (32 pollers on distinct 128B lines)
    auto wait_step = [&](int t) {
        if (tid < 32) {
            const int* f = &flags[((t & 1) * 32 + tid) * 32];
            while (ld_acquire(f) < t) { }
        }
        __syncthreads();
    };

    // ---- t = 0 : alpha0 = pi * e0 (SIMT, one-time) ----
    stage_inp(0, 0);
    stage_inp(1, 1);
    __syncthreads();
    {
        float e[2][2] = {{0.f, 0.f}, {0.f, 0.f}};
        for (int s = 0; s < NS; ++s) {
            float B0 = g_Bem[((size_t)m * NQ + p0 + pc) * NS + s];
            float B1 = g_Bem[((size_t)m * NQ + p0 + pc + 1) * NS + s];
            #pragma unroll
            for (int j = 0; j < 2; ++j) {
                unsigned short u = *(unsigned short*)(smc + OFF_INP + (bc + j) * INP_STR + s * 2);
                float x = bf2f(u);
                e[0][j] += B0 * x; e[1][j] += B1 * x;
            }
        }
        float pi0 = g_pi[m * NQ + p0 + pc], pi1 = g_pi[m * NQ + p0 + pc + 1];
        #pragma unroll
        for (int j = 0; j < 2; ++j) {
            unsigned pk = packbf(pi0 * e[0][j], pi1 * e[1][j]);
            *(unsigned*)(gA0 + (size_t)(bc + j) * NQ + p0 + pc) = pk;
        }
    }
    arrive(0);

    // ---- t = 1 .. 511 ----
    #pragma unroll 1
    for (int t = 1; t < NL; ++t) {
        const int dstb = t & 1;
        const unsigned short* srcg = dstb ? gA0 : gA1;
        unsigned short*       dstg = dstb ? gA1 : gA0;
        const bool resc = (t & 15) == 0;
        const bool pub  = (t & 15) == 15;

        // 0) wait for all step t-1 outputs
        wait_step(t - 1);

        // 1) stage alpha(t-1) into SMEM (bf16, 64 KB), async
        #pragma unroll
        for (int k = 0; k < 16; ++k) {
            int idx = k * NTH + tid;
            int b = idx >> 6, o = idx & 63;
            cp16(alp_u + b * ALP_STR + o * 16, srcg + (size_t)b * NQ + o * 8);
        }
        CP_COMMIT();

        // 2) deferred rescale factors (g_part visible after wait_step)
        if (resc && tid < NB) {
            float s = 0.f;
            const float4* pp = (const float4*)&g_part[(m * NB + tid) * 32];
            #pragma unroll
            for (int k = 0; k < 8; ++k) {
                float4 v = __ldcg(pp + k);
                s += (v.x + v.y) + (v.z + v.w);
            }
            *(float*)(smc + OFF_INV + tid * 4) = 1.0f / s;
            if (slice == 0) ll += logf(s);
        }

        // 3) emission HMMA (kq==0 warps; inp(t) staged last iteration)
        if (kq == 0) {
            float ea[16];
            #pragma unroll
            for (int i = 0; i < 16; ++i) ea[i] = 0.f;
            uint32_t ibase = inp_u + (t & 1) * 5120 + (nh * 32 + g) * INP_STR + t4 * 4;
            #pragma unroll
            for (int nt = 0; nt < 4; ++nt) {
                uint32_t ba = ibase + nt * 8 * INP_STR;
                #pragma unroll
                for (int kk = 0; kk < 2; ++kk) {
                    uint32_t b0 = lds32(ba + kk * 32);
                    uint32_t b1 = lds32(ba + kk * 32 + 16);
                    mma16816(ea + nt * 4, bem[kk], b0, b1);
                }
            }
            #pragma unroll
            for (int nt = 0; nt < 4; ++nt) {
                uint32_t wbase = e_u + (g * PRT_PSTR + nh * 32 + nt * 8 + t4 * 2) * 4;
                sts64f(wbase, ea[nt * 4 + 0], ea[nt * 4 + 1]);
                sts64f(wbase + 8 * PRT_PSTR * 4, ea[nt * 4 + 2], ea[nt * 4 + 3]);
            }
        }

        CP_WAIT0();
        __syncthreads();

        // 4) main HMMA: D partial over this warp's 128-q quarter
        {
            float da[16];
            #pragma unroll
            for (int i = 0; i < 16; ++i) da[i] = 0.f;
            uint32_t bbase = alp_u + (nh * 32 + g) * ALP_STR + kq * 256 + t4 * 4;
            #pragma unroll
            for (int nt = 0; nt < 4; ++nt) {
                uint32_t ba = bbase + nt * 8 * ALP_STR;
                #pragma unroll
                for (int kk = 0; kk < 8; ++kk) {
                    uint32_t b0 = lds32(ba + kk * 32);
                    uint32_t b1 = lds32(ba + kk * 32 + 16);
                    mma16816(da + nt * 4, af[kk], b0, b1);
                }
            }
            #pragma unroll
            for (int nt = 0; nt < 4; ++nt) {
                uint32_t wbase = part_u +
                    (kq * PRT_KSTR + g * PRT_PSTR + nh * 32 + nt * 8 + t4 * 2) * 4;
                sts64f(wbase, da[nt * 4 + 0], da[nt * 4 + 1]);
                sts64f(wbase + 8 * PRT_PSTR * 4, da[nt * 4 + 2], da[nt * 4 + 3]);
            }
        }
        __syncthreads();

        // 5) reduce 4 kq partials, multiply emission (+1/s), store bf16 alpha
        {
            float val[2][2];
            #pragma unroll
            for (int i = 0; i < 2; ++i) {
                float d0 = 0.f, d1 = 0.f, x, y;
                #pragma unroll
                for (int k2 = 0; k2 < 4; ++k2) {
                    lds64f(x, y, part_u + (k2 * PRT_KSTR + (pc + i) * PRT_PSTR + bc) * 4);
                    d0 += x; d1 += y;
                }
                lds64f(x, y, e_u + ((pc + i) * PRT_PSTR + bc) * 4);
                val[i][0] = d0 * x; val[i][1] = d1 * y;
            }
            if (resc) {
                float i0 = *(float*)(smc + OFF_INV + bc * 4);
                float i1 = *(float*)(smc + OFF_INV + bc * 4 + 4);
                val[0][0] *= i0; val[1][0] *= i0;
                val[0][1] *= i1; val[1][1] *= i1;
            }
            #pragma unroll
            for (int j = 0; j < 2; ++j) {
                unsigned pk = packbf(val[0][j], val[1][j]);
                *(unsigned*)(dstg + (size_t)(bc + j) * NQ + p0 + pc) = pk;
            }
            if (pub) {
                #pragma unroll
                for (int j = 0; j < 2; ++j)
                    *(float*)(smc + OFF_PUB + ((tid & 7) * 64 + bc + j) * 4) =
                        val[0][j] + val[1][j];
                __syncthreads();
                if (tid < NB) {
                    float s = 0.f;
                    #pragma unroll
                    for (int k = 0; k < 8; ++k)
                        s += *(float*)(smc + OFF_PUB + (k * 64 + tid) * 4);
                    g_part[(m * NB + tid) * 32 + slice] = s;
                }
            }
        }

        // 6) arrive, then stage inputs for t+1 inside the barrier window
        arrive(t);
        stage_inp(t + 1 < NL ? t + 1 : NL - 1, (t + 1) & 1);
    }

    // ---- finalize loglik (need all step-511 pubs visible) ----
    wait_step(NL - 1);
    if (slice == 0 && tid < NB) {
        float s = 0.f;
        const float4* pp = (const float4*)&g_part[(m * NB + tid) * 32];
        #pragma unroll
        for (int k = 0; k < 8; ++k) {
            float4 v = __ldcg(pp + k);
            s += (v.x + v.y) + (v.z + v.w);
        }
        out[m * NB + tid] = ll + logf(s);
    }
}

// ---------------- launch ------------------------------------------------------
extern "C" void kernel_launch(void* const* d_in, const int* in_sizes, int n_in,
                              void* d_out, int out_size) {
    (void)in_sizes; (void)n_in; (void)out_size;
    const float* inputs      = (const float*)d_in[0];
    const float* A_logits    = (const float*)d_in[1];
    const float* init_logits = (const float*)d_in[2];
    const float* em_logits   = (const float*)d_in[3];
    float* out = (float*)d_out;

    cudaFuncSetAttribute(hmm_fwd, cudaFuncAttributeMaxDynamicSharedMemorySize,
                         SMEM_BYTES);

    pre_k<<<NM * NQ + NM + NM * NQ, PTH>>>(A_logits, init_logits, em_logits);
    hmm_fwd<<<NM * 32, NTH, SMEM_BYTES>>>(inputs, out);
}

// round 17
// speedup vs baseline: 1.1672x; 1.0514x over previous
#include <cuda_runtime.h>
#include <cstdint>

#define NM 4
#define NB 64
#define NL 512
#define NQ 512
#define NS 26
#define NTH 256
#define PTH 256

// SMEM byte offsets (base is 1024-aligned)
#define OFF_ALP  0            // 64 rows x 1040 B (512 bf16 + 8 pad)
#define OFF_INP  66560        // 2 bufs x 64 rows x 80 B
#define OFF_PART 76800        // 4 kq x 16 p x 72 f32
#define OFF_E    95232        // 16 p x 72 f32
#define OFF_PUB  99840        // 8 x 64 f32
#define OFF_INV  101888       // 64 f32
#define SMEM_BYTES 102400

#define ALP_STR  1040
#define INP_STR  80
#define PRT_PSTR 72
#define PRT_KSTR 1152

// ---------------- device scratch ---------------------------------------------
__device__ float g_A[NM * NQ * NQ];
__device__ float g_pi[NM * NQ];
__device__ float g_Bem[NM * NQ * NS];
__device__ unsigned short g_alphab[NM * 2 * NB * NQ];  // bf16 alpha, dbl-buffered
__device__ float g_part[NM * NB * 32];                 // per-slice partial sums
__device__ int   g_flag[NM * 2 * 32 * 32];             // padded flags: one 128B line each

// ---------------- helpers ----------------------------------------------------
__device__ __forceinline__ uint32_t smem_u32(const void* p) {
    uint32_t a;
    asm("{ .reg .u64 t; cvta.to.shared.u64 t, %1; cvt.u32.u64 %0, t; }" : "=r"(a) : "l"(p));
    return a;
}
__device__ __forceinline__ void cp16(uint32_t dst, const void* src) {
    asm volatile("cp.async.cg.shared.global [%0], [%1], 16;" :: "r"(dst), "l"(src) : "memory");
}
#define CP_COMMIT()   asm volatile("cp.async.commit_group;" ::: "memory")
#define CP_WAIT0W()   asm volatile("cp.async.wait_group 0;" ::: "memory")

__device__ __forceinline__ unsigned packbf(float lo, float hi) {
    unsigned r;
    asm("cvt.rn.bf16x2.f32 %0, %1, %2;" : "=r"(r) : "f"(hi), "f"(lo));
    return r;
}
__device__ __forceinline__ float bf2f(unsigned short u) {
    return __uint_as_float(((unsigned)u) << 16);
}
__device__ __forceinline__ void mma16816(float* d, const uint32_t* a,
                                         uint32_t b0, uint32_t b1) {
    asm volatile(
        "mma.sync.aligned.m16n8k16.row.col.f32.bf16.bf16.f32 "
        "{%0,%1,%2,%3}, {%4,%5,%6,%7}, {%8,%9}, {%0,%1,%2,%3};"
        : "+f"(d[0]), "+f"(d[1]), "+f"(d[2]), "+f"(d[3])
        : "r"(a[0]), "r"(a[1]), "r"(a[2]), "r"(a[3]), "r"(b0), "r"(b1));
}
__device__ __forceinline__ uint32_t lds32(uint32_t addr) {
    uint32_t v;
    asm volatile("ld.shared.b32 %0, [%1];" : "=r"(v) : "r"(addr) : "memory");
    return v;
}
__device__ __forceinline__ void lds64f(float& x, float& y, uint32_t addr) {
    asm volatile("ld.shared.v2.f32 {%0,%1}, [%2];" : "=f"(x), "=f"(y) : "r"(addr) : "memory");
}
__device__ __forceinline__ void sts64f(uint32_t addr, float x, float y) {
    asm volatile("st.shared.v2.f32 [%0], {%1,%2};" :: "r"(addr), "f"(x), "f"(y) : "memory");
}
__device__ __forceinline__ void sts32(uint32_t addr, uint32_t v) {
    asm volatile("st.shared.b32 [%0], %1;" :: "r"(addr), "r"(v) : "memory");
}
__device__ __forceinline__ void st_release(int* p, int v) {
    asm volatile("st.release.gpu.global.s32 [%0], %1;" :: "l"(p), "r"(v) : "memory");
}
__device__ __forceinline__ int ld_acquire(const int* p) {
    int v;
    asm volatile("ld.acquire.gpu.global.s32 %0, [%1];" : "=r"(v) : "l"(p) : "memory");
    return v;
}

// ---------------- fused preprocessing ----------------------------------------
__global__ void pre_k(const float* __restrict__ Al, const float* __restrict__ pil,
                      const float* __restrict__ eml) {
    int r = blockIdx.x, tid = threadIdx.x;
    if (r == 0) {
        for (int i = tid; i < NM * 2 * 32 * 32; i += PTH) g_flag[i] = -1;
        for (int i = tid; i < NM * NB * 32; i += PTH) g_part[i] = 0.f;
    }
    const float* x; float* y; int len;
    if (r < NM * NQ)           { x = Al  + (size_t)r * NQ; y = g_A  + (size_t)r * NQ; len = NQ; }
    else if (r < NM * NQ + NM) { int rr = r - NM * NQ;
                                 x = pil + (size_t)rr * NQ; y = g_pi + (size_t)rr * NQ; len = NQ; }
    else                       { int rr = r - NM * NQ - NM;
                                 x = eml + (size_t)rr * NS; y = g_Bem + (size_t)rr * NS; len = NS; }
    __shared__ float red[PTH];
    float mx = -1e30f;
    for (int i = tid; i < len; i += PTH) mx = fmaxf(mx, x[i]);
    red[tid] = mx; __syncthreads();
    for (int o = PTH / 2; o > 0; o >>= 1) {
        if (tid < o) red[tid] = fmaxf(red[tid], red[tid + o]);
        __syncthreads();
    }
    mx = red[0]; __syncthreads();
    float sm = 0.f;
    for (int i = tid; i < len; i += PTH) sm += expf(x[i] - mx);
    red[tid] = sm; __syncthreads();
    for (int o = PTH / 2; o > 0; o >>= 1) {
        if (tid < o) red[tid] += red[tid + o];
        __syncthreads();
    }
    float inv = 1.0f / red[0];
    for (int i = tid; i < len; i += PTH) y[i] = expf(x[i] - mx) * inv;
}

// ---------------- main persistent kernel --------------------------------------
// grid 128 = 4 models x 32 slices (16 p each); 256 threads = 8 warps:
// warp wid = nh*4 + kq. Warp stages/consumes ONLY its 8KB alpha subtile
// (rows nh*32..+31, cols kq*128..+127) and waits only its 8 producer slices.
__global__ void __launch_bounds__(NTH, 1)
hmm_fwd(const float* __restrict__ inputs, float* __restrict__ out) {
    const int m     = blockIdx.x >> 5;
    const int slice = blockIdx.x & 31;
    const int p0    = slice * 16;
    const int tid   = threadIdx.x;
    const int wid   = tid >> 5;
    const int lane  = tid & 31;
    const int g     = lane >> 2;
    const int t4    = lane & 3;
    const int nh    = wid >> 2;
    const int kq    = wid & 3;

    extern __shared__ __align__(1024) char smc[];
    const uint32_t su     = smem_u32(smc);
    const uint32_t alp_u  = su + OFF_ALP;
    const uint32_t inp_u  = su + OFF_INP;
    const uint32_t part_u = su + OFF_PART;
    const uint32_t e_u    = su + OFF_E;

    // ---- persistent A fragments (A_sl[p][q] = g_A[m][q][p0+p]) ----
    uint32_t af[8][4];
    {
        const float* Ag = g_A + (size_t)m * NQ * NQ;
        #pragma unroll
        for (int kk = 0; kk < 8; ++kk) {
            int q0 = kq * 128 + kk * 16;
            af[kk][0] = packbf(__ldg(Ag + (size_t)(q0 + 2*t4) * NQ + p0 + g),
                               __ldg(Ag + (size_t)(q0 + 2*t4 + 1) * NQ + p0 + g));
            af[kk][1] = packbf(__ldg(Ag + (size_t)(q0 + 2*t4) * NQ + p0 + g + 8),
                               __ldg(Ag + (size_t)(q0 + 2*t4 + 1) * NQ + p0 + g + 8));
            af[kk][2] = packbf(__ldg(Ag + (size_t)(q0 + 8 + 2*t4) * NQ + p0 + g),
                               __ldg(Ag + (size_t)(q0 + 9 + 2*t4) * NQ + p0 + g));
            af[kk][3] = packbf(__ldg(Ag + (size_t)(q0 + 8 + 2*t4) * NQ + p0 + g + 8),
                               __ldg(Ag + (size_t)(q0 + 9 + 2*t4) * NQ + p0 + g + 8));
        }
    }
    // ---- Bem fragments for emission HMMA (kq==0 warps only) ----
    uint32_t bem[2][4];
    if (kq == 0) {
        #pragma unroll
        for (int kk = 0; kk < 2; ++kk) {
            int s0 = kk * 16;
            auto gB = [&](int p, int s) -> float {
                return (s < NS) ? g_Bem[((size_t)m * NQ + p0 + p) * NS + s] : 0.f;
            };
            bem[kk][0] = packbf(gB(g, s0 + 2*t4),     gB(g, s0 + 2*t4 + 1));
            bem[kk][1] = packbf(gB(g + 8, s0 + 2*t4), gB(g + 8, s0 + 2*t4 + 1));
            bem[kk][2] = packbf(gB(g, s0 + 8 + 2*t4), gB(g, s0 + 9 + 2*t4));
            bem[kk][3] = packbf(gB(g + 8, s0 + 8 + 2*t4), gB(g + 8, s0 + 9 + 2*t4));
        }
    }

    // zero inp buffers (pads must be zero), then order before stage_inp stores.
    for (int i = tid; i < 2560; i += NTH) sts32(inp_u + i * 4, 0u);
    __syncthreads();

    const float* inp_m = inputs + (size_t)m * NB * NL * NS;
    int* flags = &g_flag[m * 2 * 32 * 32];      // [par][slice], one 128B line each
    unsigned short* gA0 = g_alphab + (size_t)(m * 2 + 0) * NB * NQ;
    unsigned short* gA1 = g_alphab + (size_t)(m * 2 + 1) * NB * NQ;

    const int pc = (tid & 7) * 2;
    const int bc = (tid >> 3) * 2;
    float ll = 0.f;

    auto stage_inp = [&](int t, int buf) {
        #pragma unroll
        for (int j = 0; j < 4; ++j) {
            int idx = j * NTH + tid;
            if (idx < 832) {
                int b = idx / 13, k = idx - b * 13;
                float2 v = __ldg((const float2*)(inp_m + (size_t)b * NL * NS +
                                                 (size_t)t * NS + k * 2));
                sts32(inp_u + buf * 5120 + b * INP_STR + k * 4, packbf(v.x, v.y));
            }
        }
    };

    // ---- t = 0 : alpha0 = pi * e0 (SIMT, one-time) ----
    stage_inp(0, 0);
    stage_inp(1, 1);
    __syncthreads();
    {
        float e[2][2] = {{0.f, 0.f}, {0.f, 0.f}};
        for (int s = 0; s < NS; ++s) {
            float B0 = g_Bem[((size_t)m * NQ + p0 + pc) * NS + s];
            float B1 = g_Bem[((size_t)m * NQ + p0 + pc + 1) * NS + s];
            #pragma unroll
            for (int j = 0; j < 2; ++j) {
                unsigned short u = *(unsigned short*)(smc + OFF_INP + (bc + j) * INP_STR + s * 2);
                float x = bf2f(u);
                e[0][j] += B0 * x; e[1][j] += B1 * x;
            }
        }
        float pi0 = g_pi[m * NQ + p0 + pc], pi1 = g_pi[m * NQ + p0 + pc + 1];
        #pragma unroll
        for (int j = 0; j < 2; ++j) {
            unsigned pk = packbf(pi0 * e[0][j], pi1 * e[1][j]);
            *(unsigned*)(gA0 + (size_t)(bc + j) * NQ + p0 + pc) = pk;
        }
    }
    __syncthreads();
    if (tid == 0) st_release(&flags[(0 * 32 + slice) * 32], 0);

    // ---- t = 1 .. 511 ----
    #pragma unroll 1
    for (int t = 1; t < NL; ++t) {
        const int dstb = t & 1;
        const unsigned short* srcg = dstb ? gA0 : gA1;
        unsigned short*       dstg = dstb ? gA1 : gA0;
        const bool resc = (t & 15) == 0;
        const bool pub  = (t & 15) == 15;
        const int  pbase = ((t - 1) & 1) * 32;

        // 0) per-warp wait: only the 8 producer slices of this warp's q-quarter
        //    (all 32 on rescale steps: g_part from every slice must be visible)
        if (resc) {
            const int* f = &flags[(pbase + lane) * 32];
            while (ld_acquire(f) < t - 1) { }
        } else if (lane < 8) {
            const int* f = &flags[(pbase + kq * 8 + lane) * 32];
            while (ld_acquire(f) < t - 1) { }
        }
        __syncwarp();

        // 1) per-warp stage of own 8KB subtile (rows nh-half x cols kq-quarter)
        #pragma unroll
        for (int j = 0; j < 16; ++j) {
            int idx = j * 32 + lane;
            int bl = idx >> 4, line = idx & 15;
            cp16(alp_u + (nh * 32 + bl) * ALP_STR + kq * 256 + line * 16,
                 srcg + (size_t)(nh * 32 + bl) * NQ + kq * 128 + line * 8);
        }
        CP_COMMIT();

        // 2) deferred rescale factors (g_part visible after the wide wait)
        if (resc && tid < NB) {
            float s = 0.f;
            const float4* pp = (const float4*)&g_part[(m * NB + tid) * 32];
            #pragma unroll
            for (int k = 0; k < 8; ++k) {
                float4 v = __ldcg(pp + k);
                s += (v.x + v.y) + (v.z + v.w);
            }
            *(float*)(smc + OFF_INV + tid * 4) = 1.0f / s;
            if (slice == 0) ll += logf(s);
        }

        // 3) stage inputs for t+1 (LDG->STS; visible to all at next bar)
        stage_inp(t + 1 < NL ? t + 1 : NL - 1, (t + 1) & 1);

        // 4) emission HMMA (kq==0 warps; inp(t) staged last iteration)
        if (kq == 0) {
            float ea[16];
            #pragma unroll
            for (int i = 0; i < 16; ++i) ea[i] = 0.f;
            uint32_t ibase = inp_u + (t & 1) * 5120 + (nh * 32 + g) * INP_STR + t4 * 4;
            #pragma unroll
            for (int nt = 0; nt < 4; ++nt) {
                uint32_t ba = ibase + nt * 8 * INP_STR;
                #pragma unroll
                for (int kk = 0; kk < 2; ++kk) {
                    uint32_t b0 = lds32(ba + kk * 32);
                    uint32_t b1 = lds32(ba + kk * 32 + 16);
                    mma16816(ea + nt * 4, bem[kk], b0, b1);
                }
            }
            #pragma unroll
            for (int nt = 0; nt < 4; ++nt) {
                uint32_t wbase = e_u + (g * PRT_PSTR + nh * 32 + nt * 8 + t4 * 2) * 4;
                sts64f(wbase, ea[nt * 4 + 0], ea[nt * 4 + 1]);
                sts64f(wbase + 8 * PRT_PSTR * 4, ea[nt * 4 + 2], ea[nt * 4 + 3]);
            }
        }

        // 5) per-warp completion of own subtile, then main HMMA
        CP_WAIT0W();
        __syncwarp();
        {
            float da[16];
            #pragma unroll
            for (int i = 0; i < 16; ++i) da[i] = 0.f;
            uint32_t bbase = alp_u + (nh * 32 + g) * ALP_STR + kq * 256 + t4 * 4;
            #pragma unroll
            for (int nt = 0; nt < 4; ++nt) {
                uint32_t ba = bbase + nt * 8 * ALP_STR;
                #pragma unroll
                for (int kk = 0; kk < 8; ++kk) {
                    uint32_t b0 = lds32(ba + kk * 32);
                    uint32_t b1 = lds32(ba + kk * 32 + 16);
                    mma16816(da + nt * 4, af[kk], b0, b1);
                }
            }
            #pragma unroll
            for (int nt = 0; nt < 4; ++nt) {
                uint32_t wbase = part_u +
                    (kq * PRT_KSTR + g * PRT_PSTR + nh * 32 + nt * 8 + t4 * 2) * 4;
                sts64f(wbase, da[nt * 4 + 0], da[nt * 4 + 1]);
                sts64f(wbase + 8 * PRT_PSTR * 4, da[nt * 4 + 2], da[nt * 4 + 3]);
            }
        }
        __syncthreads();

        // 6) reduce 4 kq partials, multiply emission (+1/s), store bf16 alpha
        {
            float val[2][2];
            #pragma unroll
            for (int i = 0; i < 2; ++i) {
                float d0 = 0.f, d1 = 0.f, x, y;
                #pragma unroll
                for (int k2 = 0; k2 < 4; ++k2) {
                    lds64f(x, y, part_u + (k2 * PRT_KSTR + (pc + i) * PRT_PSTR + bc) * 4);
                    d0 += x; d1 += y;
                }
                lds64f(x, y, e_u + ((pc + i) * PRT_PSTR + bc) * 4);
                val[i][0] = d0 * x; val[i][1] = d1 * y;
            }
            if (resc) {
                float i0 = *(float*)(smc + OFF_INV + bc * 4);
                float i1 = *(float*)(smc + OFF_INV + bc * 4 + 4);
                val[0][0] *= i0; val[1][0] *= i0;
                val[0][1] *= i1; val[1][1] *= i1;
            }
            #pragma unroll
            for (int j = 0; j < 2; ++j) {
                unsigned pk = packbf(val[0][j], val[1][j]);
                *(unsigned*)(dstg + (size_t)(bc + j) * NQ + p0 + pc) = pk;
            }
            if (pub) {
                #pragma unroll
                for (int j = 0; j < 2; ++j)
                    *(float*)(smc + OFF_PUB + ((tid & 7) * 64 + bc + j) * 4) =
                        val[0][j] + val[1][j];
                __syncthreads();
                if (tid < NB) {
                    float s = 0.f;
                    #pragma unroll
                    for (int k = 0; k < 8; ++k)
                        s += *(float*)(smc + OFF_PUB + (k * 64 + tid) * 4);
                    g_part[(m * NB + tid) * 32 + slice] = s;
                }
            }
        }

        // 7) arrive: order all STGs of this CTA, then release the step flag
        __syncthreads();
        if (tid == 0) st_release(&flags[((t & 1) * 32 + slice) * 32], t);
    }

    // ---- finalize loglik (need all step-511 pubs visible) ----
    {
        const int* f = &flags[((NL - 1) & 1) * 32 * 32 + lane * 32];
        while (ld_acquire(f) < NL - 1) { }
    }
    __syncthreads();
    if (slice == 0 && tid < NB) {
        float s = 0.f;
        const float4* pp = (const float4*)&g_part[(m * NB + tid) * 32];
        #pragma unroll
        for (int k = 0; k < 8; ++k) {
            float4 v = __ldcg(pp + k);
            s += (v.x + v.y) + (v.z + v.w);
        }
        out[m * NB + tid] = ll + logf(s);
    }
}

// ---------------- launch ------------------------------------------------------
extern "C" void kernel_launch(void* const* d_in, const int* in_sizes, int n_in,
                              void* d_out, int out_size) {
    (void)in_sizes; (void)n_in; (void)out_size;
    const float* inputs      = (const float*)d_in[0];
    const float* A_logits    = (const float*)d_in[1];
    const float* init_logits = (const float*)d_in[2];
    const float* em_logits   = (const float*)d_in[3];
    float* out = (float*)d_out;

    cudaFuncSetAttribute(hmm_fwd, cudaFuncAttributeMaxDynamicSharedMemorySize,
                         SMEM_BYTES);

    pre_k<<<NM * NQ + NM + NM * NQ, PTH>>>(A_logits, init_logits, em_logits);
    hmm_fwd<<<NM * 32, NTH, SMEM_BYTES>>>(inputs, out);
}